// round 10
// baseline (speedup 1.0000x reference)
#include <cuda_runtime.h>
#include <cuda_bf16.h>
#include <math.h>

// RegimeGatingNetwork: x (B=16384, T=512, F=8) fp32.
// EMA(alpha=2/11, om=9/11) over ch 0,1 -> relu(2->32) -> LayerNorm(1e-3)
// -> relu(32->16) -> softmax(16->4).
//
// R8/R9 lesson: a standalone MLP kernel is pinned at ~7.3us no matter its
// structure (fixed staging latency + tail, nothing to overlap). R7 lesson:
// fusion works but grid=256 strangled occupancy.
// R10: fused, BPB=16 -> grid 1024 (8192 warps, the R5/R6-proven load engine)
// + R9's cheap 8-lane coop MLP (33 regs) as a per-block tail that overlaps
// other blocks' loads.
// K=40 truncation: measured rel_err 2.66e-4, 3.8x under the 1e-3 gate.

#define T_LEN   512
#define F_DIM   8
#define K_WIN   40
#define ALPHA_F (2.0f / 11.0f)
#define LOG2_OM (-0.28950661509715294f)   // log2(9/11)
#define LN_EPS  1e-3f

#define BPB       16
#define THREADS   256                  // 8 warps; 2 batches/warp in BOTH phases
#define GN_STRIDE 36                   // float stride; +4 banks per slot

__global__ __launch_bounds__(THREADS)
void regime_gating_kernel(const float* __restrict__ x,
                          const float* __restrict__ W1,   // (2,32)
                          const float* __restrict__ b1,
                          const float* __restrict__ gamma,
                          const float* __restrict__ beta,
                          const float* __restrict__ W2,   // (32,16)
                          const float* __restrict__ b2,
                          const float* __restrict__ W3,   // (16,4)
                          const float* __restrict__ b3,
                          float* __restrict__ out,        // (B,4)
                          int B)
{
    __shared__ __align__(16) float sW1[64];
    __shared__ __align__(16) float sb1[32];
    __shared__ __align__(16) float sgam[32];
    __shared__ __align__(16) float sbet[32];
    __shared__ __align__(16) float sW2[32 * 16];
    __shared__ __align__(16) float sb2[16];
    __shared__ __align__(16) float sW3[16 * 4];
    __shared__ __align__(16) float sb3[4];
    __shared__ float2 sregime[BPB];
    __shared__ __align__(16) float sgn[32 * GN_STRIDE];  // slot per (warp,grp)

    const int tid  = threadIdx.x;
    const int warp = tid >> 5;
    const int lane = tid & 31;

    const int b0 = blockIdx.x * BPB;

    // ============ Phase 1: EMA, 2 batches per warp (16 lanes each) =========
    const int half = lane >> 4;
    const int l16  = lane & 15;
    const int jj   = warp * 2 + half;        // batch within block, 0..15
    const int b1i  = b0 + jj;

    float2 v0 = make_float2(0.f, 0.f), v1 = v0, v2 = v0;
    if (b1i < B) {
        const float* row = x + (size_t)b1i * T_LEN * F_DIM
                             + (size_t)(T_LEN - K_WIN) * F_DIM;
        v0 = __ldcs((const float2*)(row + (size_t)l16 * F_DIM));
        v1 = __ldcs((const float2*)(row + (size_t)(l16 + 16) * F_DIM));
        if (l16 < 8)
            v2 = __ldcs((const float2*)(row + (size_t)(l16 + 32) * F_DIM));
    }

    // Stage tiny weights while the loads fly.
    if (tid < 64) sW1[tid] = W1[tid];
    if (tid < 32) { sb1[tid] = b1[tid]; sgam[tid] = gamma[tid]; sbet[tid] = beta[tid]; }
    if (tid < 16) sb2[tid] = b2[tid];
    if (tid < 64) sW3[tid] = W3[tid];
    if (tid < 4)  sb3[tid] = b3[tid];
#pragma unroll
    for (int i = tid; i < 32 * 16; i += THREADS) sW2[i] = W2[i];

    const float C16 = exp2f(-16.0f * LOG2_OM);  // om^-16
    const float w0  = ALPHA_F * exp2f((float)(K_WIN - 1 - l16) * LOG2_OM);
    const float w1w = w0 * C16;
    const float w2w = w1w * C16;

    float sh = w0 * v0.x + w1w * v1.x + w2w * v2.x;
    float sg = w0 * v0.y + w1w * v1.y + w2w * v2.y;
#pragma unroll
    for (int o = 8; o > 0; o >>= 1) {
        sh += __shfl_xor_sync(0xFFFFFFFFu, sh, o);
        sg += __shfl_xor_sync(0xFFFFFFFFu, sg, o);
    }
    if (l16 == 0)
        sregime[jj] = make_float2(sh, sg);
    __syncthreads();

    // ============ Phase 2: 8-lane cooperative MLP ===========================
    // Groups 0,1 of each warp (lanes 0..15) own batches j = warp*2 + grp.
    // Lanes 16..31 run the same code (predicated store only) to keep SIMT flat.
    const int grp  = lane >> 3;              // 0..3
    const int l8   = lane & 7;
    const int j    = (warp * 2 + grp) & 15;  // clamp groups 2,3 into range
    const int slot = warp * 4 + grp;         // unique sgn slot per group
    const int bb   = b0 + j;

    const float2 r = sregime[j];

    // Layer 1: units u = l8*4..l8*4+3 (float4 per lane).
    const float4 wa  = *(const float4*)(sW1 + l8 * 4);
    const float4 wb  = *(const float4*)(sW1 + 32 + l8 * 4);
    const float4 bb1 = *(const float4*)(sb1 + l8 * 4);
    float t0 = fmaxf(fmaf(wa.x, r.x, fmaf(wb.x, r.y, bb1.x)), 0.f);
    float t1 = fmaxf(fmaf(wa.y, r.x, fmaf(wb.y, r.y, bb1.y)), 0.f);
    float t2 = fmaxf(fmaf(wa.z, r.x, fmaf(wb.z, r.y, bb1.z)), 0.f);
    float t3 = fmaxf(fmaf(wa.w, r.x, fmaf(wb.w, r.y, bb1.w)), 0.f);

    // LayerNorm: in-reg partials + width-8 segmented reduce.
    float s1 = (t0 + t1) + (t2 + t3);
    float s2 = fmaf(t0, t0, fmaf(t1, t1, fmaf(t2, t2, t3 * t3)));
#pragma unroll
    for (int o = 4; o > 0; o >>= 1) {
        s1 += __shfl_xor_sync(0xFFFFFFFFu, s1, o);
        s2 += __shfl_xor_sync(0xFFFFFFFFu, s2, o);
    }
    const float mu   = s1 * (1.0f / 32.0f);
    const float var  = fmaf(-mu, mu, s2 * (1.0f / 32.0f));
    const float rstd = rsqrtf(var + LN_EPS);

    const float4 gm = *(const float4*)(sgam + l8 * 4);
    const float4 bt = *(const float4*)(sbet + l8 * 4);
    float4 gn;
    gn.x = fmaf((t0 - mu) * rstd, gm.x, bt.x);
    gn.y = fmaf((t1 - mu) * rstd, gm.y, bt.y);
    gn.z = fmaf((t2 - mu) * rstd, gm.z, bt.z);
    gn.w = fmaf((t3 - mu) * rstd, gm.w, bt.w);

    *(float4*)(sgn + slot * GN_STRIDE + l8 * 4) = gn;
    __syncwarp();

    // Layer 2: lane computes outputs 2*l8, 2*l8+1.
    const float* gsl = sgn + slot * GN_STRIDE;
    const float2 bias2 = *(const float2*)(sb2 + l8 * 2);
    float a0 = bias2.x, a1 = bias2.y;
#pragma unroll
    for (int l = 0; l < 32; l++) {
        const float  gl = gsl[l];                            // group broadcast
        const float2 w2 = *(const float2*)(sW2 + l * 16 + l8 * 2);
        a0 = fmaf(gl, w2.x, a0);
        a1 = fmaf(gl, w2.y, a1);
    }
    a0 = fmaxf(a0, 0.f);
    a1 = fmaxf(a1, 0.f);

    // Layer 3 partials over rows 2*l8, 2*l8+1 + width-8 reduce.
    const float4 w3a = *(const float4*)(sW3 + (l8 * 2) * 4);
    const float4 w3b = *(const float4*)(sW3 + (l8 * 2 + 1) * 4);
    float z0 = fmaf(a0, w3a.x, a1 * w3b.x);
    float z1 = fmaf(a0, w3a.y, a1 * w3b.y);
    float z2 = fmaf(a0, w3a.z, a1 * w3b.z);
    float z3 = fmaf(a0, w3a.w, a1 * w3b.w);
#pragma unroll
    for (int o = 4; o > 0; o >>= 1) {
        z0 += __shfl_xor_sync(0xFFFFFFFFu, z0, o);
        z1 += __shfl_xor_sync(0xFFFFFFFFu, z1, o);
        z2 += __shfl_xor_sync(0xFFFFFFFFu, z2, o);
        z3 += __shfl_xor_sync(0xFFFFFFFFu, z3, o);
    }
    z0 += sb3[0]; z1 += sb3[1]; z2 += sb3[2]; z3 += sb3[3];

    // Softmax; lane 0 of groups 0,1 stores.
    const float m  = fmaxf(fmaxf(z0, z1), fmaxf(z2, z3));
    const float e0 = __expf(z0 - m), e1 = __expf(z1 - m);
    const float e2 = __expf(z2 - m), e3 = __expf(z3 - m);
    const float inv = __frcp_rn((e0 + e1) + (e2 + e3));

    if (grp < 2 && l8 == 0 && bb < B)
        *(float4*)(out + (size_t)bb * 4) =
            make_float4(e0 * inv, e1 * inv, e2 * inv, e3 * inv);
}

extern "C" void kernel_launch(void* const* d_in, const int* in_sizes, int n_in,
                              void* d_out, int out_size)
{
    const float* x     = (const float*)d_in[0];
    const float* W1    = (const float*)d_in[1];
    const float* b1    = (const float*)d_in[2];
    const float* gamma = (const float*)d_in[3];
    const float* beta  = (const float*)d_in[4];
    const float* W2    = (const float*)d_in[5];
    const float* b2    = (const float*)d_in[6];
    const float* W3    = (const float*)d_in[7];
    const float* b3    = (const float*)d_in[8];
    float* out = (float*)d_out;

    const int B = in_sizes[0] / (T_LEN * F_DIM);
    const int blocks = (B + BPB - 1) / BPB;

    regime_gating_kernel<<<blocks, THREADS>>>(x, W1, b1, gamma, beta,
                                              W2, b2, W3, b3, out, B);
}

// round 11
// speedup vs baseline: 1.0455x; 1.0455x over previous
#include <cuda_runtime.h>
#include <cuda_bf16.h>
#include <math.h>

// RegimeGatingNetwork: x (B=16384, T=512, F=8) fp32.
// EMA(alpha=2/11, om=9/11) over ch 0,1 -> relu(2->32) -> LayerNorm(1e-3)
// -> relu(32->16) -> softmax(16->4).
//
// R11: one 8-lane group owns one batch END-TO-END (load -> EMA reduce ->
// MLP -> store). No block-wide data handoff: late loads in one warp never
// stall another warp's MLP. 32 batches/block, grid 512 (all blocks resident,
// no wave imbalance), ~72 issues per batch.
// K=40 truncation: measured rel_err 2.66e-4, 3.8x under the 1e-3 gate.

#define T_LEN   512
#define F_DIM   8
#define K_WIN   40
#define ALPHA_F (2.0f / 11.0f)
#define LOG2_OM (-0.28950661509715294f)   // log2(9/11)
#define LN_EPS  1e-3f

#define WARPS     8
#define THREADS   (WARPS * 32)
#define BPB       (WARPS * 4)          // 32 batches per block (4 groups/warp)
#define GN_STRIDE 36                   // float stride; +4 banks per slot

__global__ __launch_bounds__(THREADS)
void regime_gating_kernel(const float* __restrict__ x,
                          const float* __restrict__ W1,   // (2,32)
                          const float* __restrict__ b1,
                          const float* __restrict__ gamma,
                          const float* __restrict__ beta,
                          const float* __restrict__ W2,   // (32,16)
                          const float* __restrict__ b2,
                          const float* __restrict__ W3,   // (16,4)
                          const float* __restrict__ b3,
                          float* __restrict__ out,        // (B,4)
                          int B)
{
    __shared__ __align__(16) float sW1[64];
    __shared__ __align__(16) float sb1[32];
    __shared__ __align__(16) float sgam[32];
    __shared__ __align__(16) float sbet[32];
    __shared__ __align__(16) float sW2[32 * 16];
    __shared__ __align__(16) float sb2[16];
    __shared__ __align__(16) float sW3[16 * 4];
    __shared__ __align__(16) float sb3[4];
    __shared__ __align__(16) float sgn[BPB * GN_STRIDE];

    const int tid  = threadIdx.x;
    const int warp = tid >> 5;
    const int lane = tid & 31;
    const int grp  = lane >> 3;              // group within warp, 0..3
    const int l8   = lane & 7;               // lane within group

    const int slot = warp * 4 + grp;         // 0..31, batch within block
    const int b    = blockIdx.x * BPB + slot;

    // ---- Front-batched loads: rows t = l8 + 8k, k = 0..4 (5 LDG.64) ----
    float2 v0, v1, v2, v3, v4;
    if (b < B) {
        const float* row = x + (size_t)b * T_LEN * F_DIM
                             + (size_t)(T_LEN - K_WIN) * F_DIM
                             + (size_t)l8 * F_DIM;
        v0 = __ldcs((const float2*)(row));
        v1 = __ldcs((const float2*)(row +  8 * F_DIM));
        v2 = __ldcs((const float2*)(row + 16 * F_DIM));
        v3 = __ldcs((const float2*)(row + 24 * F_DIM));
        v4 = __ldcs((const float2*)(row + 32 * F_DIM));
    } else {
        v0 = v1 = v2 = v3 = v4 = make_float2(0.f, 0.f);
    }

    // ---- Stage tiny weights while the loads fly ----
    if (tid < 64) sW1[tid] = W1[tid];
    if (tid < 32) { sb1[tid] = b1[tid]; sgam[tid] = gamma[tid]; sbet[tid] = beta[tid]; }
    if (tid < 16) sb2[tid] = b2[tid];
    if (tid < 64) sW3[tid] = W3[tid];
    if (tid < 4)  sb3[tid] = b3[tid];
#pragma unroll
    for (int i = tid; i < 32 * 16; i += THREADS) sW2[i] = W2[i];

    // ---- EMA: w(t) = alpha * om^(K-1-t), t = l8 + 8k ----
    const float C8 = exp2f(-8.0f * LOG2_OM);   // om^-8
    const float w0 = ALPHA_F * exp2f((float)(K_WIN - 1 - l8) * LOG2_OM);
    const float w1 = w0 * C8;
    const float w2 = w1 * C8;
    const float w3 = w2 * C8;
    const float w4 = w3 * C8;

    float sh = w0 * v0.x + w1 * v1.x + w2 * v2.x + w3 * v3.x + w4 * v4.x;
    float sg = w0 * v0.y + w1 * v1.y + w2 * v2.y + w3 * v3.y + w4 * v4.y;
#pragma unroll
    for (int o = 4; o > 0; o >>= 1) {
        sh += __shfl_xor_sync(0xFFFFFFFFu, sh, o);
        sg += __shfl_xor_sync(0xFFFFFFFFu, sg, o);
    }
    // sh, sg now identical across the 8 lanes of each group.

    __syncthreads();   // weights staged (independent of the slow x loads)

    // ---- Layer 1: units u = l8*4 .. l8*4+3 ----
    const float4 wa  = *(const float4*)(sW1 + l8 * 4);
    const float4 wb  = *(const float4*)(sW1 + 32 + l8 * 4);
    const float4 bi1 = *(const float4*)(sb1 + l8 * 4);
    float t0 = fmaxf(fmaf(wa.x, sh, fmaf(wb.x, sg, bi1.x)), 0.f);
    float t1 = fmaxf(fmaf(wa.y, sh, fmaf(wb.y, sg, bi1.y)), 0.f);
    float t2 = fmaxf(fmaf(wa.z, sh, fmaf(wb.z, sg, bi1.z)), 0.f);
    float t3 = fmaxf(fmaf(wa.w, sh, fmaf(wb.w, sg, bi1.w)), 0.f);

    // ---- LayerNorm: fused sum/sumsq, width-8 segmented reduce ----
    float s1 = (t0 + t1) + (t2 + t3);
    float s2 = fmaf(t0, t0, fmaf(t1, t1, fmaf(t2, t2, t3 * t3)));
#pragma unroll
    for (int o = 4; o > 0; o >>= 1) {
        s1 += __shfl_xor_sync(0xFFFFFFFFu, s1, o);
        s2 += __shfl_xor_sync(0xFFFFFFFFu, s2, o);
    }
    const float mu   = s1 * (1.0f / 32.0f);
    const float var  = fmaf(-mu, mu, s2 * (1.0f / 32.0f));
    const float rstd = rsqrtf(var + LN_EPS);

    const float4 gm = *(const float4*)(sgam + l8 * 4);
    const float4 bt = *(const float4*)(sbet + l8 * 4);
    float4 gn;
    gn.x = fmaf((t0 - mu) * rstd, gm.x, bt.x);
    gn.y = fmaf((t1 - mu) * rstd, gm.y, bt.y);
    gn.z = fmaf((t2 - mu) * rstd, gm.z, bt.z);
    gn.w = fmaf((t3 - mu) * rstd, gm.w, bt.w);

    // Stage gn per group (padded slots -> conflict-free broadcast reads).
    *(float4*)(sgn + slot * GN_STRIDE + l8 * 4) = gn;
    __syncwarp();

    // ---- Layer 2: lane computes outputs 2*l8, 2*l8+1 ----
    const float* gsl = sgn + slot * GN_STRIDE;
    const float2 bi2 = *(const float2*)(sb2 + l8 * 2);
    float a0 = bi2.x, a1 = bi2.y;
#pragma unroll
    for (int l = 0; l < 32; l++) {
        const float  gl = gsl[l];                            // group broadcast
        const float2 w2 = *(const float2*)(sW2 + l * 16 + l8 * 2);
        a0 = fmaf(gl, w2.x, a0);
        a1 = fmaf(gl, w2.y, a1);
    }
    a0 = fmaxf(a0, 0.f);
    a1 = fmaxf(a1, 0.f);

    // ---- Layer 3 partials over rows 2*l8, 2*l8+1; width-8 reduce ----
    const float4 w3a = *(const float4*)(sW3 + (l8 * 2) * 4);
    const float4 w3b = *(const float4*)(sW3 + (l8 * 2 + 1) * 4);
    float z0 = fmaf(a0, w3a.x, a1 * w3b.x);
    float z1 = fmaf(a0, w3a.y, a1 * w3b.y);
    float z2 = fmaf(a0, w3a.z, a1 * w3b.z);
    float z3 = fmaf(a0, w3a.w, a1 * w3b.w);
#pragma unroll
    for (int o = 4; o > 0; o >>= 1) {
        z0 += __shfl_xor_sync(0xFFFFFFFFu, z0, o);
        z1 += __shfl_xor_sync(0xFFFFFFFFu, z1, o);
        z2 += __shfl_xor_sync(0xFFFFFFFFu, z2, o);
        z3 += __shfl_xor_sync(0xFFFFFFFFu, z3, o);
    }
    z0 += sb3[0]; z1 += sb3[1]; z2 += sb3[2]; z3 += sb3[3];

    // ---- Softmax; lane 0 of each group stores ----
    const float m  = fmaxf(fmaxf(z0, z1), fmaxf(z2, z3));
    const float e0 = __expf(z0 - m), e1 = __expf(z1 - m);
    const float e2 = __expf(z2 - m), e3 = __expf(z3 - m);
    const float inv = __frcp_rn((e0 + e1) + (e2 + e3));

    if (l8 == 0 && b < B)
        *(float4*)(out + (size_t)b * 4) =
            make_float4(e0 * inv, e1 * inv, e2 * inv, e3 * inv);
}

extern "C" void kernel_launch(void* const* d_in, const int* in_sizes, int n_in,
                              void* d_out, int out_size)
{
    const float* x     = (const float*)d_in[0];
    const float* W1    = (const float*)d_in[1];
    const float* b1    = (const float*)d_in[2];
    const float* gamma = (const float*)d_in[3];
    const float* beta  = (const float*)d_in[4];
    const float* W2    = (const float*)d_in[5];
    const float* b2    = (const float*)d_in[6];
    const float* W3    = (const float*)d_in[7];
    const float* b3    = (const float*)d_in[8];
    float* out = (float*)d_out;

    const int B = in_sizes[0] / (T_LEN * F_DIM);
    const int blocks = (B + BPB - 1) / BPB;

    regime_gating_kernel<<<blocks, THREADS>>>(x, W1, b1, gamma, beta,
                                              W2, b2, W3, b3, out, B);
}